// round 1
// baseline (speedup 1.0000x reference)
#include <cuda_runtime.h>
#include <cuda_bf16.h>
#include <math.h>

// Problem constants
#define NN 13
#define BB 2
#define TT 2048
#define DD 1024
#define ROW_F4 (DD / 4)          // 256 float4 per (n,b,t) row
#define THREADS 256
#define EPS 1.1920928955078125e-07f   // FLT_EPSILON = jnp.finfo(f32).eps

__global__ __launch_bounds__(THREADS, 2)
void attn_res_block_kernel(const float4* __restrict__ V,
                           const float4* __restrict__ rms_w,
                           const float4* __restrict__ w_proj,
                           float4* __restrict__ out)
{
    const int bt  = blockIdx.x;          // 0 .. B*T-1 (4096)
    const int tid = threadIdx.x;         // 0 .. 255, owns float4 at d = tid*4
    const int lane = tid & 31;
    const int wid  = tid >> 5;           // 0..7

    // Combined weight for this thread's 4 channels
    float4 rw = rms_w[tid];
    float4 wp = w_proj[tid];
    const float w0 = rw.x * wp.x;
    const float w1 = rw.y * wp.y;
    const float w2 = rw.z * wp.z;
    const float w3 = rw.w * wp.w;

    // Load all 13 depth rows for this (b,t); keep in registers.
    // V float4 index: (n*B*T + bt)*ROW_F4 + tid   (max 13.6M, fits int)
    float4 v[NN];
    float ss[NN];   // partial sum of squares
    float dp[NN];   // partial dot with combined weight
    #pragma unroll
    for (int n = 0; n < NN; n++) {
        float4 x = V[(n * (BB * TT) + bt) * ROW_F4 + tid];
        v[n] = x;
        ss[n] = x.x * x.x + x.y * x.y + x.z * x.z + x.w * x.w;
        dp[n] = x.x * w0  + x.y * w1  + x.z * w2  + x.w * w3;
    }

    // Warp-level reduction of the 26 partials
    #pragma unroll
    for (int n = 0; n < NN; n++) {
        #pragma unroll
        for (int off = 16; off > 0; off >>= 1) {
            ss[n] += __shfl_xor_sync(0xFFFFFFFFu, ss[n], off);
            dp[n] += __shfl_xor_sync(0xFFFFFFFFu, dp[n], off);
        }
    }

    // Cross-warp reduction via shared memory
    __shared__ float s_ss[NN][8];
    __shared__ float s_dp[NN][8];
    if (lane == 0) {
        #pragma unroll
        for (int n = 0; n < NN; n++) {
            s_ss[n][wid] = ss[n];
            s_dp[n][wid] = dp[n];
        }
    }
    __syncthreads();

    // Every thread computes logits + softmax redundantly (13 elems — cheap)
    float logit[NN];
    float mx = -INFINITY;
    #pragma unroll
    for (int n = 0; n < NN; n++) {
        float tss = 0.f, tdp = 0.f;
        #pragma unroll
        for (int k = 0; k < 8; k++) {
            tss += s_ss[n][k];
            tdp += s_dp[n][k];
        }
        float ms = tss * (1.0f / DD) + EPS;      // mean(V^2) + eps
        float l  = rsqrtf(ms) * tdp;             // rsqrt * dot
        logit[n] = l;
        mx = fmaxf(mx, l);
    }
    float denom = 0.f;
    float a[NN];
    #pragma unroll
    for (int n = 0; n < NN; n++) {
        a[n] = __expf(logit[n] - mx);
        denom += a[n];
    }
    const float inv = 1.0f / denom;

    // Weighted sum of UN-normalized V rows (still in registers)
    float4 o = make_float4(0.f, 0.f, 0.f, 0.f);
    #pragma unroll
    for (int n = 0; n < NN; n++) {
        float an = a[n] * inv;
        o.x += an * v[n].x;
        o.y += an * v[n].y;
        o.z += an * v[n].z;
        o.w += an * v[n].w;
    }
    out[bt * ROW_F4 + tid] = o;
}

extern "C" void kernel_launch(void* const* d_in, const int* in_sizes, int n_in,
                              void* d_out, int out_size)
{
    const float4* V      = (const float4*)d_in[0];   // [13,2,2048,1024] f32
    const float4* rms_w  = (const float4*)d_in[1];   // [1024] f32
    const float4* w_proj = (const float4*)d_in[2];   // [1024] f32
    float4* out          = (float4*)d_out;           // [2,2048,1024] f32

    attn_res_block_kernel<<<BB * TT, THREADS>>>(V, rms_w, w_proj, out);
}